// round 4
// baseline (speedup 1.0000x reference)
#include <cuda_runtime.h>
#include <math.h>

#define NMAX   8192
#define KMAX   64
#define NBINS  1024
#define ATHR   1024      // threads for binning kernel (== NBINS)
#define BBLK   128       // threads for KDE/final kernel

// Scratch (__device__ globals: allocation-free rule)
__device__ float g_coefA[KMAX];        // w_k / sqrt(2*pi*var_k)
__device__ float g_coefB[KMAX];        // -0.5 / var_k
__device__ float g_xs[NMAX];           // sorted-by-bin x, pre-scaled to exp2 domain
__device__ float g_xo[NMAX];           // sorted-by-bin x, original values
__device__ int   g_binstart[NBINS + 1];
__device__ float g_minS, g_wS;         // bin origin/width in scaled domain

__device__ __forceinline__ float ex2f(float e) {
    float r;
    asm("ex2.approx.ftz.f32 %0, %1;" : "=f"(r) : "f"(e));
    return r;
}

// ---------------------------------------------------------------------------
// Kernel A (single block, 1024 thr): min/max -> bin histogram -> scan ->
// scatter (counting sort), plus softmax prep and out zeroing.
// ---------------------------------------------------------------------------
__global__ void k_bin(const float* __restrict__ x,
                      const float* __restrict__ wl,
                      const float* __restrict__ lv,
                      float* __restrict__ out,
                      int n, int K, float scaleS) {
    __shared__ float red[ATHR];
    __shared__ int   cnt[NBINS];
    __shared__ int   tmp[NBINS];
    __shared__ int   start[NBINS + 1];
    int t = threadIdx.x;

    // ---- min / max ----
    float mn = 3.0e38f, mx = -3.0e38f;
    for (int i = t; i < n; i += ATHR) {
        float v = x[i];
        mn = fminf(mn, v);
        mx = fmaxf(mx, v);
    }
    red[t] = mn; __syncthreads();
#pragma unroll
    for (int o = ATHR / 2; o > 0; o >>= 1) {
        if (t < o) red[t] = fminf(red[t], red[t + o]);
        __syncthreads();
    }
    float gmn = red[0]; __syncthreads();
    red[t] = mx; __syncthreads();
#pragma unroll
    for (int o = ATHR / 2; o > 0; o >>= 1) {
        if (t < o) red[t] = fmaxf(red[t], red[t + o]);
        __syncthreads();
    }
    float gmx = red[0]; __syncthreads();
    float w = (gmx > gmn) ? (gmx - gmn) / (float)NBINS : 1.0f;
    float invw = 1.0f / w;

    // ---- bin counts ----
    cnt[t] = 0;
    __syncthreads();
    for (int i = t; i < n; i += ATHR) {
        int b = (int)((x[i] - gmn) * invw);
        b = max(0, min(NBINS - 1, b));
        atomicAdd(&cnt[b], 1);
    }
    __syncthreads();

    // ---- inclusive scan (Hillis-Steele) ----
    tmp[t] = cnt[t];
    __syncthreads();
#pragma unroll
    for (int o = 1; o < NBINS; o <<= 1) {
        int add = (t >= o) ? tmp[t - o] : 0;
        __syncthreads();
        tmp[t] += add;
        __syncthreads();
    }
    if (t == 0) start[0] = 0;
    start[t + 1] = tmp[t];
    __syncthreads();

    // ---- scatter (cursor = cnt reused) ----
    cnt[t] = start[t];
    __syncthreads();
    for (int i = t; i < n; i += ATHR) {
        float xv = x[i];
        int b = (int)((xv - gmn) * invw);
        b = max(0, min(NBINS - 1, b));
        int pos = atomicAdd(&cnt[b], 1);
        g_xs[pos] = xv * scaleS;
        g_xo[pos] = xv;
    }
    g_binstart[t + 1] = start[t + 1];
    if (t == 0) {
        g_binstart[0] = 0;
        g_minS = gmn * scaleS;
        g_wS   = w * scaleS;
        *out = 0.0f;
    }

    // ---- softmax prep (all threads participate in reductions) ----
    float wv = (t < K) ? wl[t] : -INFINITY;
    __syncthreads();
    red[t] = wv; __syncthreads();
#pragma unroll
    for (int o = ATHR / 2; o > 0; o >>= 1) {
        if (t < o) red[t] = fmaxf(red[t], red[t + o]);
        __syncthreads();
    }
    float m = red[0]; __syncthreads();
    float e = (t < K) ? __expf(wv - m) : 0.0f;
    red[t] = e; __syncthreads();
#pragma unroll
    for (int o = ATHR / 2; o > 0; o >>= 1) {
        if (t < o) red[t] += red[t + o];
        __syncthreads();
    }
    if (t < K) {
        float wt  = e / red[0];
        float var = __expf(lv[t]);
        g_coefA[t] = wt * rsqrtf(2.0f * (float)M_PI * var);
        g_coefB[t] = -0.5f / var;
    }
}

// ---------------------------------------------------------------------------
// Kernel B: windowed KDE + mixture pdf + squared-error reduction.
// Works entirely in sorted order (the final sum is permutation-invariant).
// ---------------------------------------------------------------------------
__global__ void k_kdefin(const float* __restrict__ means,
                         float* __restrict__ out,
                         int n, int K, float invC) {
    __shared__ float cA[KMAX], cB[KMAX], mu[KMAX];
    __shared__ float red[BBLK];
    int t = threadIdx.x;
    if (t < K) {
        cA[t] = g_coefA[t];
        cB[t] = g_coefB[t];
        mu[t] = means[t];
    }
    __syncthreads();

    int j = blockIdx.x * BBLK + t;
    float val = 0.0f;
    if (j < n) {
        float xs   = g_xs[j];
        float minS = g_minS;
        float invw = 1.0f / g_wS;
        const float RS = 6.5f;   // scaled cutoff radius: dropped terms < 2^-42

        int lo = (int)((xs - RS - minS) * invw);
        int hi = (int)((xs + RS - minS) * invw);
        lo = max(0, min(NBINS - 1, lo));
        hi = max(0, min(NBINS - 1, hi));
        int i0 = g_binstart[lo];
        int i1 = g_binstart[hi + 1];

        float s0 = 0.0f, s1 = 0.0f;
        int i = i0;
        for (; i + 1 < i1; i += 2) {
            float d0 = xs - g_xs[i];
            float d1 = xs - g_xs[i + 1];
            s0 += ex2f(-d0 * d0);
            s1 += ex2f(-d1 * d1);
        }
        if (i < i1) {
            float d = xs - g_xs[i];
            s0 += ex2f(-d * d);
        }
        float data = (s0 + s1) * invC;

        float xo = g_xo[j];
        float mix = 0.0f;
#pragma unroll 8
        for (int k = 0; k < KMAX; k++) {
            if (k < K) {
                float d = xo - mu[k];
                mix += cA[k] * __expf(cB[k] * d * d);
            }
        }
        float err = mix - data;
        val = err * err;
    }

    red[t] = val;
    __syncthreads();
#pragma unroll
    for (int o = BBLK / 2; o > 0; o >>= 1) {
        if (t < o) red[t] += red[t + o];
        __syncthreads();
    }
    if (t == 0) atomicAdd(out, red[0]);
}

// ---------------------------------------------------------------------------
extern "C" void kernel_launch(void* const* d_in, const int* in_sizes, int n_in,
                              void* d_out, int out_size) {
    const float* x     = (const float*)d_in[0];
    const float* wl    = (const float*)d_in[1];
    const float* means = (const float*)d_in[2];
    const float* lv    = (const float*)d_in[3];
    float* out = (float*)d_out;

    int n = in_sizes[0];   // 8192
    int K = in_sizes[1];   // 64

    // bandwidth = 0.5 * 128 / n  (= 2^-7 for n = 8192)
    double bw    = 64.0 / (double)n;
    double bw2   = bw * bw;
    double Ckde  = -0.5 / bw2;
    double LOG2E = 1.4426950408889634;
    float  scaleS = (float)sqrt(-Ckde * LOG2E);   // exp2-domain prescale
    float  invC   = (float)(1.0 / (sqrt(2.0 * M_PI * bw2) * (double)n));

    k_bin<<<1, ATHR>>>(x, wl, lv, out, n, K, scaleS);
    k_kdefin<<<(n + BBLK - 1) / BBLK, BBLK>>>(means, out, n, K, invC);
}

// round 8
// speedup vs baseline: 1.5000x; 1.5000x over previous
#include <cuda_runtime.h>
#include <math.h>

#define NMAX   8192
#define KMAX   64
#define NBINS  1024
#define ATHR   1024      // threads for binning kernel (== NBINS)
#define JB     64        // j-points per KDE block
#define TSUB   4         // threads cooperating per j
#define BBLK   (JB * TSUB)   // 256

// Scratch (__device__ globals: allocation-free rule)
__device__ float g_coefA[KMAX];        // w_k / sqrt(2*pi*var_k)
__device__ float g_coefB[KMAX];        // -0.5 / var_k
__device__ float g_xs[NMAX];           // bin-sorted x, pre-scaled to exp2 domain
__device__ float g_xo[NMAX];           // bin-sorted x, original values
__device__ int   g_binstart[NBINS + 1];
__device__ float g_minS, g_wS;         // bin origin/width in scaled domain

__device__ __forceinline__ float ex2f(float e) {
    float r;
    asm("ex2.approx.ftz.f32 %0, %1;" : "=f"(r) : "f"(e));
    return r;
}

// ---------------------------------------------------------------------------
// Kernel A (single block, 1024 thr): min/max -> histogram -> hierarchical
// scan -> scatter (counting sort) + softmax prep + out zeroing.
// All reductions/scans are warp-shuffle based: ~12 barriers total.
// ---------------------------------------------------------------------------
__global__ void k_bin(const float* __restrict__ x,
                      const float* __restrict__ wl,
                      const float* __restrict__ lv,
                      float* __restrict__ out,
                      int n, int K, float scaleS) {
    __shared__ float smn[32], smx[32];
    __shared__ int   cnt[NBINS];
    __shared__ int   wsum[32];
    __shared__ int   cursor[NBINS];
    int t = threadIdx.x, lane = t & 31, wid = t >> 5;

    // ---- min / max (warp shfl + 32-entry combine) ----
    float mn = 3.0e38f, mx = -3.0e38f;
    for (int i = t; i < n; i += ATHR) {
        float v = x[i];
        mn = fminf(mn, v);
        mx = fmaxf(mx, v);
    }
#pragma unroll
    for (int o = 16; o; o >>= 1) {
        mn = fminf(mn, __shfl_xor_sync(~0u, mn, o));
        mx = fmaxf(mx, __shfl_xor_sync(~0u, mx, o));
    }
    if (lane == 0) { smn[wid] = mn; smx[wid] = mx; }
    __syncthreads();
    if (wid == 0) {
        float a = smn[lane], b = smx[lane];
#pragma unroll
        for (int o = 16; o; o >>= 1) {
            a = fminf(a, __shfl_xor_sync(~0u, a, o));
            b = fmaxf(b, __shfl_xor_sync(~0u, b, o));
        }
        if (lane == 0) { smn[0] = a; smx[0] = b; }
    }
    __syncthreads();
    float gmn = smn[0], gmx = smx[0];
    float w = (gmx > gmn) ? (gmx - gmn) / (float)NBINS : 1.0f;
    float invw = 1.0f / w;

    // ---- histogram ----
    cnt[t] = 0;
    __syncthreads();
    for (int i = t; i < n; i += ATHR) {
        int b = min(NBINS - 1, max(0, (int)((x[i] - gmn) * invw)));
        atomicAdd(&cnt[b], 1);
    }
    __syncthreads();

    // ---- hierarchical exclusive scan of cnt ----
    int c = cnt[t];
    int incl = c;
#pragma unroll
    for (int o = 1; o < 32; o <<= 1) {
        int v = __shfl_up_sync(~0u, incl, o);
        if (lane >= o) incl += v;
    }
    if (lane == 31) wsum[wid] = incl;
    __syncthreads();
    if (wid == 0) {
        int s = wsum[lane];
#pragma unroll
        for (int o = 1; o < 32; o <<= 1) {
            int v = __shfl_up_sync(~0u, s, o);
            if (lane >= o) s += v;
        }
        wsum[lane] = s;
    }
    __syncthreads();
    int off   = (wid > 0) ? wsum[wid - 1] : 0;
    int bstart = incl + off - c;       // exclusive scan value = bin start
    cursor[t] = bstart;
    g_binstart[t] = bstart;
    if (t == ATHR - 1) g_binstart[NBINS] = incl + off;   // == n
    __syncthreads();

    // ---- scatter ----
    for (int i = t; i < n; i += ATHR) {
        float xv = x[i];
        int b = min(NBINS - 1, max(0, (int)((xv - gmn) * invw)));
        int pos = atomicAdd(&cursor[b], 1);
        g_xs[pos] = xv * scaleS;
        g_xo[pos] = xv;
    }

    // ---- softmax prep (shfl reductions, smn/smx reused after barrier) ----
    __syncthreads();
    float wv = (t < K) ? wl[t] : -INFINITY;
    float m = wv;
#pragma unroll
    for (int o = 16; o; o >>= 1) m = fmaxf(m, __shfl_xor_sync(~0u, m, o));
    if (lane == 0) smn[wid] = m;
    __syncthreads();
    if (wid == 0) {
        float v = smn[lane];
#pragma unroll
        for (int o = 16; o; o >>= 1) v = fmaxf(v, __shfl_xor_sync(~0u, v, o));
        smn[0] = v;
    }
    __syncthreads();
    m = smn[0];
    float e = (t < K) ? __expf(wv - m) : 0.0f;
    float s = e;
#pragma unroll
    for (int o = 16; o; o >>= 1) s += __shfl_xor_sync(~0u, s, o);
    if (lane == 0) smx[wid] = s;
    __syncthreads();
    if (wid == 0) {
        float v = smx[lane];
#pragma unroll
        for (int o = 16; o; o >>= 1) v += __shfl_xor_sync(~0u, v, o);
        smx[0] = v;
    }
    __syncthreads();
    if (t < K) {
        float wt  = e / smx[0];
        float var = __expf(lv[t]);
        g_coefA[t] = wt * rsqrtf(2.0f * (float)M_PI * var);
        g_coefB[t] = -0.5f / var;
    }
    if (t == 0) {
        g_minS = gmn * scaleS;
        g_wS   = w * scaleS;
        *out = 0.0f;
    }
}

// ---------------------------------------------------------------------------
// Kernel B: windowed KDE + mixture pdf + squared-error reduction.
// 4 threads cooperate per j-point (shfl combine); 256-thr blocks cover 64 j's.
// ---------------------------------------------------------------------------
__global__ void k_kdefin(const float* __restrict__ means,
                         float* __restrict__ out,
                         int n, int K, float invC) {
    __shared__ float cA[KMAX], cB[KMAX], mu[KMAX];
    __shared__ float red[JB];
    int t = threadIdx.x;
    if (t < KMAX) {
        cA[t] = g_coefA[t];
        cB[t] = g_coefB[t];
        mu[t] = means[t];
    }
    __syncthreads();

    int jl = t >> 2, ts = t & (TSUB - 1);
    int j  = blockIdx.x * JB + jl;

    float kde = 0.0f, mix = 0.0f;
    if (j < n) {
        float xs = g_xs[j];
        float xo = g_xo[j];
        float minS = g_minS;
        float invw = 1.0f / g_wS;
        const float RS = 6.5f;   // scaled cutoff: dropped terms < 2^-42

        int lo = min(NBINS - 1, max(0, (int)((xs - RS - minS) * invw)));
        int hi = min(NBINS - 1, max(0, (int)((xs + RS - minS) * invw)));
        int i0 = g_binstart[lo];
        int i1 = g_binstart[hi + 1];

        // this thread handles i = i0+ts, i0+ts+4, ... ; 2 accumulators
        float k0 = 0.0f, k1 = 0.0f;
        int i = i0 + ts;
        for (; i + TSUB < i1; i += 2 * TSUB) {
            float d0 = xs - g_xs[i];
            float d1 = xs - g_xs[i + TSUB];
            k0 += ex2f(-d0 * d0);
            k1 += ex2f(-d1 * d1);
        }
        if (i < i1) {
            float d = xs - g_xs[i];
            k0 += ex2f(-d * d);
        }
        kde = k0 + k1;

        for (int k = ts; k < K; k += TSUB) {
            float d = xo - mu[k];
            mix += cA[k] * __expf(cB[k] * d * d);
        }
    }

    // combine the 4 cooperating threads (adjacent lanes)
    kde += __shfl_xor_sync(~0u, kde, 1);
    mix += __shfl_xor_sync(~0u, mix, 1);
    kde += __shfl_xor_sync(~0u, kde, 2);
    mix += __shfl_xor_sync(~0u, mix, 2);

    float val = 0.0f;
    if (j < n) {
        float e = mix - kde * invC;
        val = e * e;
    }
    if (ts == 0) red[jl] = val;
    __syncthreads();

    // reduce 64 partials (2 warps)
    if (t < JB) {
        float v = red[t];
#pragma unroll
        for (int o = 16; o; o >>= 1) v += __shfl_xor_sync(~0u, v, o);
        if ((t & 31) == 0) red[t] = v;   // red[0], red[32]
    }
    __syncthreads();
    if (t == 0) atomicAdd(out, red[0] + red[32]);
}

// ---------------------------------------------------------------------------
extern "C" void kernel_launch(void* const* d_in, const int* in_sizes, int n_in,
                              void* d_out, int out_size) {
    const float* x     = (const float*)d_in[0];
    const float* wl    = (const float*)d_in[1];
    const float* means = (const float*)d_in[2];
    const float* lv    = (const float*)d_in[3];
    float* out = (float*)d_out;

    int n = in_sizes[0];   // 8192
    int K = in_sizes[1];   // 64

    // bandwidth = 0.5 * 128 / n  (= 2^-7 for n = 8192)
    double bw    = 64.0 / (double)n;
    double bw2   = bw * bw;
    double Ckde  = -0.5 / bw2;
    double LOG2E = 1.4426950408889634;
    float  scaleS = (float)sqrt(-Ckde * LOG2E);   // exp2-domain prescale
    float  invC   = (float)(1.0 / (sqrt(2.0 * M_PI * bw2) * (double)n));

    k_bin<<<1, ATHR>>>(x, wl, lv, out, n, K, scaleS);
    k_kdefin<<<(n + JB - 1) / JB, BBLK>>>(means, out, n, K, invC);
}

// round 11
// speedup vs baseline: 1.8427x; 1.2285x over previous
#include <cuda_runtime.h>
#include <math.h>

#define NMAX   8192
#define KMAX   64
#define NBINS  1024
#define JB     32        // j-points per block in the KDE phase
#define TSUB   8         // threads cooperating per j
#define BLK    256

// Scratch (__device__ globals: allocation-free rule)
__device__ float    g_xs[NMAX];            // bin-sorted x, exp2-domain scaled
__device__ float    g_xo[NMAX];            // bin-sorted x, original
__device__ int      g_cnt[NBINS];          // histogram (zeroed in-kernel for replays)
__device__ int      g_cursor[NBINS];       // scatter cursors
__device__ int      g_binstart[NBINS + 1];
__device__ unsigned g_bar;                 // monotone grid-barrier counter

__device__ __forceinline__ float ex2f(float e) {
    float r;
    asm("ex2.approx.ftz.f32 %0, %1;" : "=f"(r) : "f"(e));
    return r;
}

// Software grid barrier: monotone counter, release-arrive / acquire-spin.
// Safe only because all blocks are co-resident (see __launch_bounds__).
__device__ __forceinline__ void gridbar(unsigned nb) {
    __syncthreads();
    if (threadIdx.x == 0) {
        __threadfence();
        unsigned t = atomicAdd(&g_bar, 1u) + 1u;
        unsigned goal = ((t + nb - 1u) / nb) * nb;   // this barrier's completion count
        unsigned v;
        do {
            asm volatile("ld.acquire.gpu.global.u32 %0, [%1];" : "=r"(v) : "l"(&g_bar));
        } while (v < goal);
    }
    __syncthreads();
}

__global__ void __launch_bounds__(BLK, 2)
k_fused(const float* __restrict__ x,
        const float* __restrict__ wl,
        const float* __restrict__ means,
        const float* __restrict__ lv,
        float* __restrict__ out,
        int n, int K, float scaleS, float invC) {
    __shared__ float cA[KMAX], cB[KMAX], mu[KMAX];
    __shared__ float sred[32];
    int t = threadIdx.x, lane = t & 31, wid = t >> 5;
    unsigned nb = gridDim.x;
    int b = blockIdx.x;

    const float RLO = -8.0f;
    const float WBIN = 16.0f / (float)NBINS;     // fixed range [-8, 8]
    const float INVW = (float)NBINS / 16.0f;

    if (b == 0 && t == 0) *out = 0.0f;

    // ---- per-block softmax prep (cheap, removes a cross-phase dependency) ----
    float wv = (t < K) ? wl[t] : -INFINITY;
    float m = wv;
#pragma unroll
    for (int o = 16; o; o >>= 1) m = fmaxf(m, __shfl_xor_sync(~0u, m, o));
    if (lane == 0) sred[wid] = m;
    __syncthreads();
    if (wid == 0) {
        float v = (lane < BLK / 32) ? sred[lane] : -INFINITY;
#pragma unroll
        for (int o = 16; o; o >>= 1) v = fmaxf(v, __shfl_xor_sync(~0u, v, o));
        if (lane == 0) sred[0] = v;
    }
    __syncthreads();
    m = sred[0];
    float e = (t < K) ? __expf(wv - m) : 0.0f;
    float s = e;
#pragma unroll
    for (int o = 16; o; o >>= 1) s += __shfl_xor_sync(~0u, s, o);
    __syncthreads();                 // protect sred reuse
    if (lane == 0) sred[wid] = s;
    __syncthreads();
    if (wid == 0) {
        float v = (lane < BLK / 32) ? sred[lane] : 0.0f;
#pragma unroll
        for (int o = 16; o; o >>= 1) v += __shfl_xor_sync(~0u, v, o);
        if (lane == 0) sred[0] = v;
    }
    __syncthreads();
    if (t < K) {
        float wt  = e / sred[0];
        float var = __expf(lv[t]);
        cA[t] = wt * rsqrtf(2.0f * (float)M_PI * var);
        cB[t] = -0.5f / var;
        mu[t] = means[t];
    }

    // ---- phase 1: histogram of this block's slice ----
    int sl  = (n + (int)nb - 1) / (int)nb;        // elements per block (32)
    int i0s = b * sl;
    int i1s = min(n, i0s + sl);
    for (int i = i0s + t; i < i1s; i += BLK) {
        int bin = min(NBINS - 1, max(0, (int)((x[i] - RLO) * INVW)));
        atomicAdd(&g_cnt[bin], 1);
    }
    gridbar(nb);

    // ---- phase 2: block 0 scans histogram -> binstart/cursors, re-zeros cnt ----
    if (b == 0) {
        int c[4], loc = 0;
#pragma unroll
        for (int q = 0; q < 4; q++) { c[q] = g_cnt[t * 4 + q]; loc += c[q]; }
        int incl = loc;
#pragma unroll
        for (int o = 1; o < 32; o <<= 1) {
            int v = __shfl_up_sync(~0u, incl, o);
            if (lane >= o) incl += v;
        }
        __shared__ int wsum[8];
        if (lane == 31) wsum[wid] = incl;
        __syncthreads();
        if (wid == 0 && lane < 8) {
            int v = wsum[lane];
#pragma unroll
            for (int o = 1; o < 8; o <<= 1) {
                int u = __shfl_up_sync(0xffu, v, o);
                if (lane >= o) v += u;
            }
            wsum[lane] = v;
        }
        __syncthreads();
        int base = incl - loc + ((wid > 0) ? wsum[wid - 1] : 0);  // exclusive start
#pragma unroll
        for (int q = 0; q < 4; q++) {
            g_binstart[t * 4 + q] = base;
            g_cursor[t * 4 + q]   = base;
            base += c[q];
            g_cnt[t * 4 + q] = 0;                  // clean for next graph replay
        }
        if (t == BLK - 1) g_binstart[NBINS] = n;
    }
    gridbar(nb);

    // ---- phase 3: scatter (counting sort) ----
    for (int i = i0s + t; i < i1s; i += BLK) {
        float xv = x[i];
        int bin = min(NBINS - 1, max(0, (int)((xv - RLO) * INVW)));
        int pos = atomicAdd(&g_cursor[bin], 1);
        g_xs[pos] = xv * scaleS;
        g_xo[pos] = xv;
    }
    gridbar(nb);

    // ---- phase 4: windowed KDE + mixture pdf + squared-error reduction ----
    int jl = t >> 3, ts = t & (TSUB - 1);
    int j  = b * JB + jl;

    float kde = 0.0f, mix = 0.0f;
    if (j < n) {
        float xs   = g_xs[j];
        float minS = RLO * scaleS;
        float invwS = 1.0f / (WBIN * scaleS);
        const float RS = 6.5f;       // scaled cutoff: dropped terms < 2^-42

        int lo = min(NBINS - 1, max(0, (int)((xs - RS - minS) * invwS)));
        int hi = min(NBINS - 1, max(0, (int)((xs + RS - minS) * invwS)));
        int i0 = g_binstart[lo];
        int i1 = g_binstart[hi + 1];

        float k0 = 0.0f, k1 = 0.0f;
        int i = i0 + ts;
        for (; i + TSUB < i1; i += 2 * TSUB) {
            float d0 = xs - g_xs[i];
            float d1 = xs - g_xs[i + TSUB];
            k0 += ex2f(-d0 * d0);
            k1 += ex2f(-d1 * d1);
        }
        if (i < i1) {
            float d = xs - g_xs[i];
            k0 += ex2f(-d * d);
        }
        kde = k0 + k1;

        float xo = g_xo[j];
        for (int k = ts; k < K; k += TSUB) {
            float d = xo - mu[k];
            mix += cA[k] * __expf(cB[k] * d * d);
        }
    }

    // combine the 8 cooperating lanes
#pragma unroll
    for (int o = 1; o < TSUB; o <<= 1) {
        kde += __shfl_xor_sync(~0u, kde, o);
        mix += __shfl_xor_sync(~0u, mix, o);
    }

    float val = 0.0f;
    if (j < n && ts == 0) {
        float err = mix - kde * invC;
        val = err * err;
    }
    // block sum: warp reduce (non-ts0 lanes carry 0), then 8-warp combine
#pragma unroll
    for (int o = 16; o; o >>= 1) val += __shfl_xor_sync(~0u, val, o);
    __syncthreads();                 // sred reuse
    if (lane == 0) sred[wid] = val;
    __syncthreads();
    if (wid == 0) {
        float v = (lane < BLK / 32) ? sred[lane] : 0.0f;
#pragma unroll
        for (int o = 16; o; o >>= 1) v += __shfl_xor_sync(~0u, v, o);
        if (lane == 0) atomicAdd(out, v);
    }
}

// ---------------------------------------------------------------------------
extern "C" void kernel_launch(void* const* d_in, const int* in_sizes, int n_in,
                              void* d_out, int out_size) {
    const float* x     = (const float*)d_in[0];
    const float* wl    = (const float*)d_in[1];
    const float* means = (const float*)d_in[2];
    const float* lv    = (const float*)d_in[3];
    float* out = (float*)d_out;

    int n = in_sizes[0];   // 8192
    int K = in_sizes[1];   // 64

    // bandwidth = 0.5 * 128 / n  (= 2^-7 for n = 8192)
    double bw    = 64.0 / (double)n;
    double bw2   = bw * bw;
    double Ckde  = -0.5 / bw2;
    double LOG2E = 1.4426950408889634;
    float  scaleS = (float)sqrt(-Ckde * LOG2E);   // exp2-domain prescale
    float  invC   = (float)(1.0 / (sqrt(2.0 * M_PI * bw2) * (double)n));

    int nb = (n + JB - 1) / JB;                   // 256 blocks for n=8192
    k_fused<<<nb, BLK>>>(x, wl, means, lv, out, n, K, scaleS, invC);
}